// round 15
// baseline (speedup 1.0000x reference)
#include <cuda_runtime.h>
#include <cuda_fp16.h>
#include <cstdint>

// ============================================================================
// ECGRGNN via warp-level mma.sync (base sm_100; tcgen05 unavailable here).
//
// R15: GRU kernel byte-identical to R11/R14 (98.5% of the sm_100 HMMA
// roofline, 512 MAC/cyc/SM; all in-loop restructures and FMA-offload
// variants evaluated and rejected on cycle arithmetic). Head kernel gains
// ILP-2 split accumulators in both k-loops (halves the serial FMA chains,
// ~1e-7 rounding perturbation) on top of the R14 one-wave layout.
// ============================================================================

#define T_LEN 500
#define N_NODES 6144
#define NCTA 128
#define NODES_CTA 48
#define CTA_THREADS 384

#define ROW_STRIDE 144               // 128B data + 16B pad: 4-bank rotation/row

typedef uint32_t u32;

__device__ float g_h[N_NODES * 64];

// ---------------- SMEM layout (byte offsets) ----------------
#define SM_W    0                    // 192 rows x 144B               27648
#define SM_H    27648                // 2 buf x 48x144B               13824
#define H_BUF_BYTES 6912             // one buffer (fp16 h)
#define SM_X    41472                // 500 x 48 f32                  96000
#define SMEM_TOTAL 137472

// ---------------- helpers ----------------

__device__ __forceinline__ u32 smem_u32(const void* p) {
    u32 a;
    asm("{ .reg .u64 t; cvta.to.shared.u64 t, %1; cvt.u32.u64 %0, t; }" : "=r"(a) : "l"(p));
    return a;
}

__device__ __forceinline__ void ldsm_x4(u32* r, u32 addr) {
    asm volatile("ldmatrix.sync.aligned.m8n8.x4.shared.b16 {%0,%1,%2,%3}, [%4];"
        : "=r"(r[0]), "=r"(r[1]), "=r"(r[2]), "=r"(r[3]) : "r"(addr));
}
__device__ __forceinline__ void ldsm_x2(u32* r, u32 addr) {
    asm volatile("ldmatrix.sync.aligned.m8n8.x2.shared.b16 {%0,%1}, [%2];"
        : "=r"(r[0]), "=r"(r[1]) : "r"(addr));
}
__device__ __forceinline__ void mma16816(float* d, const u32* a, const u32* b) {
    asm volatile("mma.sync.aligned.m16n8k16.row.col.f32.f16.f16.f32 "
        "{%0,%1,%2,%3}, {%4,%5,%6,%7}, {%8,%9}, {%0,%1,%2,%3};"
        : "+f"(d[0]), "+f"(d[1]), "+f"(d[2]), "+f"(d[3])
        : "r"(a[0]), "r"(a[1]), "r"(a[2]), "r"(a[3]), "r"(b[0]), "r"(b[1]));
}

// MUFU-native tanh (1 op); sigmoid via tanh identity (1 MUFU + FMA)
__device__ __forceinline__ float tanha(float x) {
    float r;
    asm("tanh.approx.f32 %0, %1;" : "=f"(r) : "f"(x));
    return r;
}
__device__ __forceinline__ float sigm(float v) {
    return fmaf(0.5f, tanha(0.5f * v), 0.5f);
}

// ---------------- GRU kernel (byte-identical to R11/R14) ----------------

__global__ void __launch_bounds__(CTA_THREADS, 1)
gru_mma_kernel(const float* __restrict__ x_raw,
               const float* __restrict__ w_ih,
               const float* __restrict__ w_hh,
               const float* __restrict__ b_ih,
               const float* __restrict__ b_hh)
{
    extern __shared__ char sm[];
    const u32 smb = smem_u32(sm);
    const int tid = threadIdx.x;
    const int lane = tid & 31;
    const int wid = tid >> 5;
    const int q = wid & 3;                  // m-tile selector (gate-row block)
    const int grp = wid >> 2;               // group 0..2 -> node tiles {2g, 2g+1}
    const int nt0 = grp * 2;
    const int bar_id = 1 + grp;
    const int gn0 = blockIdx.x * NODES_CTA;

    // ---- stage W_hh fp16 (192 x 64, 144B row stride) ----
    for (int i = tid; i < 192 * 64; i += CTA_THREADS) {
        int r = i >> 6, k = i & 63;
        *(__half*)(sm + SM_W + (u32)(r * ROW_STRIDE + k * 2)) = __float2half_rn(w_hh[i]);
    }
    // ---- zero h tiles (both buffers) ----
    for (int i = tid; i < 13824 / 4; i += CTA_THREADS)
        ((u32*)(sm + SM_H))[i] = 0u;
    // ---- stage x transposed: xs[t*48 + n] ----
    {
        float* xs = (float*)(sm + SM_X);
        for (int i = tid; i < NODES_CTA * T_LEN; i += CTA_THREADS) {
            int n = i / T_LEN, tt = i - n * T_LEN;
            xs[tt * NODES_CTA + n] = x_raw[(size_t)(gn0 + n) * T_LEN + tt];
        }
    }
    __syncthreads();

    // ---- preload W fragments (A operand, row-major m16n8k16) ----
    u32 wa[3][4][4];
    {
        int g = lane >> 3;
        int sub_m = (g & 1) * 8;
        int sub_kb = (g >> 1) * 16;
#pragma unroll
        for (int mt = 0; mt < 3; mt++) {
            int row = 64 * mt + 16 * q + sub_m + (lane & 7);
            u32 base = smb + SM_W + (u32)row * ROW_STRIDE;
#pragma unroll
            for (int kc = 0; kc < 4; kc++)
                ldsm_x4(wa[mt][kc], base + (u32)(kc * 32 + sub_kb));
        }
    }

    // ---- per-thread gate constants: units u_a = 16q + lane/4, u_b = u_a+8 ----
    const int u_a = 16 * q + (lane >> 2);
    const int u_b = u_a + 8;
    const float cwr_a = w_ih[u_a],        cwr_b = w_ih[u_b];
    const float cwz_a = w_ih[64 + u_a],   cwz_b = w_ih[64 + u_b];
    const float cwn_a = w_ih[128 + u_a],  cwn_b = w_ih[128 + u_b];
    const float cr_a  = b_ih[u_a] + b_hh[u_a];
    const float cr_b  = b_ih[u_b] + b_hh[u_b];
    const float cz_a  = b_ih[64 + u_a] + b_hh[64 + u_a];
    const float cz_b  = b_ih[64 + u_b] + b_hh[64 + u_b];
    const float cbin_a = b_ih[128 + u_a], cbin_b = b_ih[128 + u_b];
    const float cbhn_a = b_hh[128 + u_a], cbhn_b = b_hh[128 + u_b];

    // ---- h-fragment (B operand) lane addressing ----
    const int l15 = lane & 15;
    const int r7 = l15 & 7;
    u32 ko[4];
#pragma unroll
    for (int kc = 0; kc < 4; kc++)
        ko[kc] = (u32)(kc * 32 + ((l15 >> 3) * 16));
    const u32 hrow_off = (u32)r7 * ROW_STRIDE;

    const int nc = 2 * (lane & 3);
    const float* xs = (const float*)(sm + SM_X);

    float hprev[2][4];
#pragma unroll
    for (int j = 0; j < 2; j++)
#pragma unroll
        for (int i = 0; i < 4; i++) hprev[j][i] = 0.0f;

#pragma unroll 1
    for (int t = 0; t < T_LEN; t++) {
        const int buf = t & 1;
        const u32 rd = smb + SM_H + (u32)buf * H_BUF_BYTES;
        char* wr = sm + SM_H + (buf ^ 1) * H_BUF_BYTES;
        const float* xrow = xs + t * NODES_CTA;

#pragma unroll
        for (int j = 0; j < 2; j++) {
            const int nt = nt0 + j;
            // ---- load h fragments for this tile ----
            u32 hh[4][2];
            u32 base = (u32)(nt * 8) * ROW_STRIDE + hrow_off;
#pragma unroll
            for (int kc = 0; kc < 4; kc++)
                ldsm_x2(hh[kc], rd + base + ko[kc]);
            // ---- 1-term mma: 3 accumulator chains interleaved ----
            float acc[3][4];
#pragma unroll
            for (int mt = 0; mt < 3; mt++)
#pragma unroll
                for (int i = 0; i < 4; i++) acc[mt][i] = 0.0f;
#pragma unroll
            for (int kc = 0; kc < 4; kc++) {
#pragma unroll
                for (int mt = 0; mt < 3; mt++)
                    mma16816(acc[mt], wa[mt][kc], hh[kc]);
            }
            // ---- gates (registers only; tanh.approx MUFU path) ----
            const int n_a = nt * 8 + nc;
            const float xva = xrow[n_a];
            const float xvb = xrow[n_a + 1];
#pragma unroll
            for (int i = 0; i < 4; i++) {
                const bool ub = (i >= 2);
                const float x = (i & 1) ? xvb : xva;
                const float cwr = ub ? cwr_b : cwr_a;
                const float cwz = ub ? cwz_b : cwz_a;
                const float cwn = ub ? cwn_b : cwn_a;
                const float cr  = ub ? cr_b  : cr_a;
                const float cz  = ub ? cz_b  : cz_a;
                const float cbin = ub ? cbin_b : cbin_a;
                const float cbhn = ub ? cbhn_b : cbhn_a;

                float rr = sigm(acc[0][i] + fmaf(x, cwr, cr));
                float zz = sigm(acc[1][i] + fmaf(x, cwz, cz));
                float nn = tanha(fmaf(rr, acc[2][i] + cbhn, fmaf(x, cwn, cbin)));
                float hp = hprev[j][i];
                float hn = fmaf(zz, hp - nn, nn);
                hprev[j][i] = hn;

                int node = n_a + (i & 1);
                int u = ub ? u_b : u_a;
                u32 off = (u32)(node * ROW_STRIDE + u * 2);
                *(__half*)(wr + off) = __float2half_rn(hn);
            }
        }
        // per-group barrier (groups are independent: disjoint h tiles)
        asm volatile("bar.sync %0, %1;" :: "r"(bar_id), "r"(128) : "memory");
    }

    // ---- write final h ----
#pragma unroll
    for (int j = 0; j < 2; j++) {
#pragma unroll
        for (int i = 0; i < 4; i++) {
            int node = (nt0 + j) * 8 + nc + (i & 1);
            int u = (i >= 2) ? u_b : u_a;
            g_h[(size_t)(gn0 + node) * 64 + u] = hprev[j][i];
        }
    }
}

// ---------------- collapsed GCN head: one wave, 4 graphs per CTA ----------
// out[g] = relu(relu(mean_12 h @ W1 + b1) @ W2 + b2) @ Wfc + bfc
// ILP-2 split accumulators halve the serial FMA chains.

__global__ void __launch_bounds__(256)
head_kernel(const float* __restrict__ W1, const float* __restrict__ b1,
            const float* __restrict__ W2, const float* __restrict__ b2,
            const float* __restrict__ Wfc, const float* __restrict__ bfc,
            float* __restrict__ out)
{
    __shared__ float hbar[4 * 64];
    __shared__ float x1s[4 * 128];
    __shared__ float x2s[4 * 128];
    const int tid = threadIdx.x;
    const int g0 = blockIdx.x * 4;          // graphs g0..g0+3

    // ---- mean over 12 leads (ILP-2 over leads) ----
    {
        int g2 = tid >> 6, u = tid & 63;
        const float* hb = g_h + (size_t)(g0 + g2) * 12 * 64 + u;
        float s0 = 0.0f, s1 = 0.0f;
#pragma unroll
        for (int l = 0; l < 12; l += 2) {
            s0 += hb[l * 64];
            s1 += hb[(l + 1) * 64];
        }
        hbar[tid] = (s0 + s1) * (1.0f / 12.0f);
    }
    __syncthreads();

    // ---- layer 1: 4 x 128 outputs, 2 rounds, ILP-2 over k ----
#pragma unroll
    for (int r = 0; r < 2; r++) {
        int it = r * 256 + tid;
        int g2 = it >> 7, c = it & 127;
        float s0 = b1[c], s1 = 0.0f;
#pragma unroll
        for (int k = 0; k < 64; k += 2) {
            s0 = fmaf(hbar[g2 * 64 + k],     W1[k * 128 + c],       s0);
            s1 = fmaf(hbar[g2 * 64 + k + 1], W1[(k + 1) * 128 + c], s1);
        }
        x1s[it] = fmaxf(s0 + s1, 0.0f);
    }
    __syncthreads();

    // ---- layer 2: 4 x 128 outputs, 2 rounds, ILP-2 over k ----
#pragma unroll
    for (int r = 0; r < 2; r++) {
        int it = r * 256 + tid;
        int g2 = it >> 7, c = it & 127;
        float s0 = b2[c], s1 = 0.0f;
#pragma unroll
        for (int k = 0; k < 128; k += 2) {
            s0 = fmaf(x1s[g2 * 128 + k],     W2[k * 128 + c],       s0);
            s1 = fmaf(x1s[g2 * 128 + k + 1], W2[(k + 1) * 128 + c], s1);
        }
        x2s[it] = fmaxf(s0 + s1, 0.0f);
    }
    __syncthreads();

    // ---- fc: 4 graphs x 5 classes, ILP-2 over k ----
    if (tid < 20) {
        int g2 = tid / 5, c = tid - g2 * 5;
        float o0 = bfc[c], o1 = 0.0f;
#pragma unroll
        for (int k = 0; k < 128; k += 2) {
            o0 = fmaf(x2s[g2 * 128 + k],     Wfc[k * 5 + c],       o0);
            o1 = fmaf(x2s[g2 * 128 + k + 1], Wfc[(k + 1) * 5 + c], o1);
        }
        out[(g0 + g2) * 5 + c] = o0 + o1;
    }
}

// ---------------- launch ----------------
// metadata order: 0 x_raw, 1 edge_index, 2 batch, 3 w_ih, 4 w_hh, 5 b_ih,
//                 6 b_hh, 7 W1, 8 b1, 9 W2, 10 b2, 11 Wfc, 12 bfc

extern "C" void kernel_launch(void* const* d_in, const int* in_sizes, int n_in,
                              void* d_out, int out_size)
{
    const float* x_raw = (const float*)d_in[0];
    const float* w_ih  = (const float*)d_in[3];
    const float* w_hh  = (const float*)d_in[4];
    const float* b_ih  = (const float*)d_in[5];
    const float* b_hh  = (const float*)d_in[6];
    const float* W1    = (const float*)d_in[7];
    const float* b1    = (const float*)d_in[8];
    const float* W2    = (const float*)d_in[9];
    const float* b2    = (const float*)d_in[10];
    const float* Wfc   = (const float*)d_in[11];
    const float* bfc   = (const float*)d_in[12];
    float* out = (float*)d_out;

    cudaFuncSetAttribute(gru_mma_kernel, cudaFuncAttributeMaxDynamicSharedMemorySize, SMEM_TOTAL);

    gru_mma_kernel<<<NCTA, CTA_THREADS, SMEM_TOTAL>>>(x_raw, w_ih, w_hh, b_ih, b_hh);
    head_kernel<<<NCTA, 256>>>(W1, b1, W2, b2, Wfc, bfc, out);
}

// round 16
// speedup vs baseline: 1.0062x; 1.0062x over previous
#include <cuda_runtime.h>
#include <cuda_fp16.h>
#include <cstdint>

// ============================================================================
// ECGRGNN via warp-level mma.sync (base sm_100; tcgen05 unavailable here).
//
// R16: GRU kernel byte-identical to R11/R14 (98.5% of the sm_100 HMMA
// roofline, 512 MAC/cyc/SM). Head = R15 one-wave layout. NEW: programmatic
// dependent launch (griddepcontrol, base sm_90 PTX) overlaps the head's
// launch/rasterization with the GRU tail:
//   GRU: cudaTriggerProgrammaticLaunchCompletion() after g_h stores
//   head: launched with ProgrammaticStreamSerialization, calls
//         cudaGridDependencySynchronize() before reading g_h.
// Correctness is unconditional (device-side sync guarantees visibility).
// ============================================================================

#define T_LEN 500
#define N_NODES 6144
#define NCTA 128
#define NODES_CTA 48
#define CTA_THREADS 384

#define ROW_STRIDE 144               // 128B data + 16B pad: 4-bank rotation/row

typedef uint32_t u32;

__device__ float g_h[N_NODES * 64];

// ---------------- SMEM layout (byte offsets) ----------------
#define SM_W    0                    // 192 rows x 144B               27648
#define SM_H    27648                // 2 buf x 48x144B               13824
#define H_BUF_BYTES 6912             // one buffer (fp16 h)
#define SM_X    41472                // 500 x 48 f32                  96000
#define SMEM_TOTAL 137472

// ---------------- helpers ----------------

__device__ __forceinline__ u32 smem_u32(const void* p) {
    u32 a;
    asm("{ .reg .u64 t; cvta.to.shared.u64 t, %1; cvt.u32.u64 %0, t; }" : "=r"(a) : "l"(p));
    return a;
}

__device__ __forceinline__ void ldsm_x4(u32* r, u32 addr) {
    asm volatile("ldmatrix.sync.aligned.m8n8.x4.shared.b16 {%0,%1,%2,%3}, [%4];"
        : "=r"(r[0]), "=r"(r[1]), "=r"(r[2]), "=r"(r[3]) : "r"(addr));
}
__device__ __forceinline__ void ldsm_x2(u32* r, u32 addr) {
    asm volatile("ldmatrix.sync.aligned.m8n8.x2.shared.b16 {%0,%1}, [%2];"
        : "=r"(r[0]), "=r"(r[1]) : "r"(addr));
}
__device__ __forceinline__ void mma16816(float* d, const u32* a, const u32* b) {
    asm volatile("mma.sync.aligned.m16n8k16.row.col.f32.f16.f16.f32 "
        "{%0,%1,%2,%3}, {%4,%5,%6,%7}, {%8,%9}, {%0,%1,%2,%3};"
        : "+f"(d[0]), "+f"(d[1]), "+f"(d[2]), "+f"(d[3])
        : "r"(a[0]), "r"(a[1]), "r"(a[2]), "r"(a[3]), "r"(b[0]), "r"(b[1]));
}

// MUFU-native tanh (1 op); sigmoid via tanh identity (1 MUFU + FMA)
__device__ __forceinline__ float tanha(float x) {
    float r;
    asm("tanh.approx.f32 %0, %1;" : "=f"(r) : "f"(x));
    return r;
}
__device__ __forceinline__ float sigm(float v) {
    return fmaf(0.5f, tanha(0.5f * v), 0.5f);
}

// ---------------- GRU kernel (R11 body + PDL trigger) ----------------

__global__ void __launch_bounds__(CTA_THREADS, 1)
gru_mma_kernel(const float* __restrict__ x_raw,
               const float* __restrict__ w_ih,
               const float* __restrict__ w_hh,
               const float* __restrict__ b_ih,
               const float* __restrict__ b_hh)
{
    extern __shared__ char sm[];
    const u32 smb = smem_u32(sm);
    const int tid = threadIdx.x;
    const int lane = tid & 31;
    const int wid = tid >> 5;
    const int q = wid & 3;                  // m-tile selector (gate-row block)
    const int grp = wid >> 2;               // group 0..2 -> node tiles {2g, 2g+1}
    const int nt0 = grp * 2;
    const int bar_id = 1 + grp;
    const int gn0 = blockIdx.x * NODES_CTA;

    // ---- stage W_hh fp16 (192 x 64, 144B row stride) ----
    for (int i = tid; i < 192 * 64; i += CTA_THREADS) {
        int r = i >> 6, k = i & 63;
        *(__half*)(sm + SM_W + (u32)(r * ROW_STRIDE + k * 2)) = __float2half_rn(w_hh[i]);
    }
    // ---- zero h tiles (both buffers) ----
    for (int i = tid; i < 13824 / 4; i += CTA_THREADS)
        ((u32*)(sm + SM_H))[i] = 0u;
    // ---- stage x transposed: xs[t*48 + n] ----
    {
        float* xs = (float*)(sm + SM_X);
        for (int i = tid; i < NODES_CTA * T_LEN; i += CTA_THREADS) {
            int n = i / T_LEN, tt = i - n * T_LEN;
            xs[tt * NODES_CTA + n] = x_raw[(size_t)(gn0 + n) * T_LEN + tt];
        }
    }
    __syncthreads();

    // ---- preload W fragments (A operand, row-major m16n8k16) ----
    u32 wa[3][4][4];
    {
        int g = lane >> 3;
        int sub_m = (g & 1) * 8;
        int sub_kb = (g >> 1) * 16;
#pragma unroll
        for (int mt = 0; mt < 3; mt++) {
            int row = 64 * mt + 16 * q + sub_m + (lane & 7);
            u32 base = smb + SM_W + (u32)row * ROW_STRIDE;
#pragma unroll
            for (int kc = 0; kc < 4; kc++)
                ldsm_x4(wa[mt][kc], base + (u32)(kc * 32 + sub_kb));
        }
    }

    // ---- per-thread gate constants: units u_a = 16q + lane/4, u_b = u_a+8 ----
    const int u_a = 16 * q + (lane >> 2);
    const int u_b = u_a + 8;
    const float cwr_a = w_ih[u_a],        cwr_b = w_ih[u_b];
    const float cwz_a = w_ih[64 + u_a],   cwz_b = w_ih[64 + u_b];
    const float cwn_a = w_ih[128 + u_a],  cwn_b = w_ih[128 + u_b];
    const float cr_a  = b_ih[u_a] + b_hh[u_a];
    const float cr_b  = b_ih[u_b] + b_hh[u_b];
    const float cz_a  = b_ih[64 + u_a] + b_hh[64 + u_a];
    const float cz_b  = b_ih[64 + u_b] + b_hh[64 + u_b];
    const float cbin_a = b_ih[128 + u_a], cbin_b = b_ih[128 + u_b];
    const float cbhn_a = b_hh[128 + u_a], cbhn_b = b_hh[128 + u_b];

    // ---- h-fragment (B operand) lane addressing ----
    const int l15 = lane & 15;
    const int r7 = l15 & 7;
    u32 ko[4];
#pragma unroll
    for (int kc = 0; kc < 4; kc++)
        ko[kc] = (u32)(kc * 32 + ((l15 >> 3) * 16));
    const u32 hrow_off = (u32)r7 * ROW_STRIDE;

    const int nc = 2 * (lane & 3);
    const float* xs = (const float*)(sm + SM_X);

    float hprev[2][4];
#pragma unroll
    for (int j = 0; j < 2; j++)
#pragma unroll
        for (int i = 0; i < 4; i++) hprev[j][i] = 0.0f;

#pragma unroll 1
    for (int t = 0; t < T_LEN; t++) {
        const int buf = t & 1;
        const u32 rd = smb + SM_H + (u32)buf * H_BUF_BYTES;
        char* wr = sm + SM_H + (buf ^ 1) * H_BUF_BYTES;
        const float* xrow = xs + t * NODES_CTA;

#pragma unroll
        for (int j = 0; j < 2; j++) {
            const int nt = nt0 + j;
            // ---- load h fragments for this tile ----
            u32 hh[4][2];
            u32 base = (u32)(nt * 8) * ROW_STRIDE + hrow_off;
#pragma unroll
            for (int kc = 0; kc < 4; kc++)
                ldsm_x2(hh[kc], rd + base + ko[kc]);
            // ---- 1-term mma: 3 accumulator chains interleaved ----
            float acc[3][4];
#pragma unroll
            for (int mt = 0; mt < 3; mt++)
#pragma unroll
                for (int i = 0; i < 4; i++) acc[mt][i] = 0.0f;
#pragma unroll
            for (int kc = 0; kc < 4; kc++) {
#pragma unroll
                for (int mt = 0; mt < 3; mt++)
                    mma16816(acc[mt], wa[mt][kc], hh[kc]);
            }
            // ---- gates (registers only; tanh.approx MUFU path) ----
            const int n_a = nt * 8 + nc;
            const float xva = xrow[n_a];
            const float xvb = xrow[n_a + 1];
#pragma unroll
            for (int i = 0; i < 4; i++) {
                const bool ub = (i >= 2);
                const float x = (i & 1) ? xvb : xva;
                const float cwr = ub ? cwr_b : cwr_a;
                const float cwz = ub ? cwz_b : cwz_a;
                const float cwn = ub ? cwn_b : cwn_a;
                const float cr  = ub ? cr_b  : cr_a;
                const float cz  = ub ? cz_b  : cz_a;
                const float cbin = ub ? cbin_b : cbin_a;
                const float cbhn = ub ? cbhn_b : cbhn_a;

                float rr = sigm(acc[0][i] + fmaf(x, cwr, cr));
                float zz = sigm(acc[1][i] + fmaf(x, cwz, cz));
                float nn = tanha(fmaf(rr, acc[2][i] + cbhn, fmaf(x, cwn, cbin)));
                float hp = hprev[j][i];
                float hn = fmaf(zz, hp - nn, nn);
                hprev[j][i] = hn;

                int node = n_a + (i & 1);
                int u = ub ? u_b : u_a;
                u32 off = (u32)(node * ROW_STRIDE + u * 2);
                *(__half*)(wr + off) = __float2half_rn(hn);
            }
        }
        // per-group barrier (groups are independent: disjoint h tiles)
        asm volatile("bar.sync %0, %1;" :: "r"(bar_id), "r"(128) : "memory");
    }

    // ---- write final h ----
#pragma unroll
    for (int j = 0; j < 2; j++) {
#pragma unroll
        for (int i = 0; i < 4; i++) {
            int node = (nt0 + j) * 8 + nc + (i & 1);
            int u = (i >= 2) ? u_b : u_a;
            g_h[(size_t)(gn0 + node) * 64 + u] = hprev[j][i];
        }
    }

    // ---- PDL: allow the head kernel's grid to launch under our tail ----
    cudaTriggerProgrammaticLaunchCompletion();
}

// ---------------- collapsed GCN head: one wave, 4 graphs per CTA ----------
// out[g] = relu(relu(mean_12 h @ W1 + b1) @ W2 + b2) @ Wfc + bfc
// ILP-2 split accumulators; gridDependencySynchronize before g_h reads.

__global__ void __launch_bounds__(256)
head_kernel(const float* __restrict__ W1, const float* __restrict__ b1,
            const float* __restrict__ W2, const float* __restrict__ b2,
            const float* __restrict__ Wfc, const float* __restrict__ bfc,
            float* __restrict__ out)
{
    __shared__ float hbar[4 * 64];
    __shared__ float x1s[4 * 128];
    __shared__ float x2s[4 * 128];
    const int tid = threadIdx.x;
    const int g0 = blockIdx.x * 4;          // graphs g0..g0+3

    // ---- wait for GRU's g_h to be visible (PDL) ----
    cudaGridDependencySynchronize();

    // ---- mean over 12 leads (ILP-2 over leads) ----
    {
        int g2 = tid >> 6, u = tid & 63;
        const float* hb = g_h + (size_t)(g0 + g2) * 12 * 64 + u;
        float s0 = 0.0f, s1 = 0.0f;
#pragma unroll
        for (int l = 0; l < 12; l += 2) {
            s0 += hb[l * 64];
            s1 += hb[(l + 1) * 64];
        }
        hbar[tid] = (s0 + s1) * (1.0f / 12.0f);
    }
    __syncthreads();

    // ---- layer 1: 4 x 128 outputs, 2 rounds, ILP-2 over k ----
#pragma unroll
    for (int r = 0; r < 2; r++) {
        int it = r * 256 + tid;
        int g2 = it >> 7, c = it & 127;
        float s0 = b1[c], s1 = 0.0f;
#pragma unroll
        for (int k = 0; k < 64; k += 2) {
            s0 = fmaf(hbar[g2 * 64 + k],     W1[k * 128 + c],       s0);
            s1 = fmaf(hbar[g2 * 64 + k + 1], W1[(k + 1) * 128 + c], s1);
        }
        x1s[it] = fmaxf(s0 + s1, 0.0f);
    }
    __syncthreads();

    // ---- layer 2: 4 x 128 outputs, 2 rounds, ILP-2 over k ----
#pragma unroll
    for (int r = 0; r < 2; r++) {
        int it = r * 256 + tid;
        int g2 = it >> 7, c = it & 127;
        float s0 = b2[c], s1 = 0.0f;
#pragma unroll
        for (int k = 0; k < 128; k += 2) {
            s0 = fmaf(x1s[g2 * 128 + k],     W2[k * 128 + c],       s0);
            s1 = fmaf(x1s[g2 * 128 + k + 1], W2[(k + 1) * 128 + c], s1);
        }
        x2s[it] = fmaxf(s0 + s1, 0.0f);
    }
    __syncthreads();

    // ---- fc: 4 graphs x 5 classes, ILP-2 over k ----
    if (tid < 20) {
        int g2 = tid / 5, c = tid - g2 * 5;
        float o0 = bfc[c], o1 = 0.0f;
#pragma unroll
        for (int k = 0; k < 128; k += 2) {
            o0 = fmaf(x2s[g2 * 128 + k],     Wfc[k * 5 + c],       o0);
            o1 = fmaf(x2s[g2 * 128 + k + 1], Wfc[(k + 1) * 5 + c], o1);
        }
        out[(g0 + g2) * 5 + c] = o0 + o1;
    }
}

// ---------------- launch ----------------
// metadata order: 0 x_raw, 1 edge_index, 2 batch, 3 w_ih, 4 w_hh, 5 b_ih,
//                 6 b_hh, 7 W1, 8 b1, 9 W2, 10 b2, 11 Wfc, 12 bfc

extern "C" void kernel_launch(void* const* d_in, const int* in_sizes, int n_in,
                              void* d_out, int out_size)
{
    const float* x_raw = (const float*)d_in[0];
    const float* w_ih  = (const float*)d_in[3];
    const float* w_hh  = (const float*)d_in[4];
    const float* b_ih  = (const float*)d_in[5];
    const float* b_hh  = (const float*)d_in[6];
    const float* W1    = (const float*)d_in[7];
    const float* b1    = (const float*)d_in[8];
    const float* W2    = (const float*)d_in[9];
    const float* b2    = (const float*)d_in[10];
    const float* Wfc   = (const float*)d_in[11];
    const float* bfc   = (const float*)d_in[12];
    float* out = (float*)d_out;

    cudaFuncSetAttribute(gru_mma_kernel, cudaFuncAttributeMaxDynamicSharedMemorySize, SMEM_TOTAL);

    gru_mma_kernel<<<NCTA, CTA_THREADS, SMEM_TOTAL>>>(x_raw, w_ih, w_hh, b_ih, b_hh);

    // head with programmatic dependent launch (overlaps GRU tail)
    cudaLaunchConfig_t cfg = {};
    cfg.gridDim = dim3(NCTA, 1, 1);
    cfg.blockDim = dim3(256, 1, 1);
    cfg.dynamicSmemBytes = 0;
    cfg.stream = 0;
    cudaLaunchAttribute attrs[1];
    attrs[0].id = cudaLaunchAttributeProgrammaticStreamSerialization;
    attrs[0].val.programmaticStreamSerializationAllowed = 1;
    cfg.attrs = attrs;
    cfg.numAttrs = 1;
    cudaLaunchKernelEx(&cfg, head_kernel, W1, b1, W2, b2, Wfc, bfc, out);
}